// round 1
// baseline (speedup 1.0000x reference)
#include <cuda_runtime.h>

#define T_STEPS 200
#define R_N 512
#define BR_N 4
#define B_N 32
#define F_N 128
#define C_N 10
#define U_N 2048   /* R*BR */
#define K2 1024    /* 2R   */
#define NZ 256     /* nonzeros per unit (mask guarantees) */
#define VTH 0.5f

// -------- persistent device scratch (allocation-free rule) --------
__device__ float g_curT[T_STEPS * R_N * B_N];   // currents transposed [t][r][b]
__device__ float g_gT[T_STEPS * R_N * B_N];     // gating transposed  [t][r][b]
__device__ float g_wc[U_N * NZ];                // compacted weights
__device__ int   g_ic[U_N * NZ];                // compacted indices (spk idx pre-shifted by -512)
__device__ int   g_ncur[U_N];                   // #indices that hit current-half
__device__ float g_spk[2][R_N * B_N];           // spike state ping-pong [r][b]
__device__ float g_mem[R_N * B_N];              // soma membrane [r][b]
__device__ float g_din[U_N * B_N];              // dendritic state [unit][b]
__device__ float g_memo[B_N * C_N];             // readout membrane
__device__ float g_spko[B_N * C_N];             // readout spike
__device__ float g_alpha[R_N];
__device__ float g_beta[U_N];
__device__ float g_alphao[C_N];

__device__ __forceinline__ float sigmoidf(float x) { return 1.f / (1.f + expf(-x)); }

// -------- K0: compact masked weights (one warp per output unit) --------
__global__ void k_compact(const float* __restrict__ w_rnn,
                          const float* __restrict__ mask) {
    int j = blockIdx.x;          // 0..2047
    int lane = threadIdx.x;      // 0..31
    int base = 0;
    for (int c = 0; c < 32; c++) {
        int k = c * 32 + lane;
        float m = mask[j * K2 + k];
        bool nz = (m != 0.f);
        unsigned bal = __ballot_sync(0xFFFFFFFFu, nz);
        int pos = base + __popc(bal & ((1u << lane) - 1u));
        if (nz) {
            g_wc[j * NZ + pos] = w_rnn[j * K2 + k] * m;
            g_ic[j * NZ + pos] = (k < R_N) ? k : (k - R_N);
        }
        base += __popc(bal);
        if (c == 15 && lane == 0) g_ncur[j] = base;  // count of idx < 512
    }
}

// -------- K0b: zero state + precompute decays --------
__global__ void k_init(const float* __restrict__ tau_m,
                       const float* __restrict__ tau_n,
                       const float* __restrict__ tau_m_ro) {
    int tid = blockIdx.x * blockDim.x + threadIdx.x;
    if (tid < U_N * B_N) g_din[tid] = 0.f;
    if (tid < R_N * B_N) { g_mem[tid] = 0.f; g_spk[0][tid] = 0.f; }
    if (tid < B_N * C_N) { g_memo[tid] = 0.f; g_spko[tid] = 0.f; }
    if (tid < R_N)  g_alpha[tid]  = sigmoidf(tau_m[tid]);
    if (tid < U_N)  g_beta[tid]   = sigmoidf(tau_n[tid]);   // tau_n row-major [R][BR] == unit index
    if (tid < C_N)  g_alphao[tid] = sigmoidf(tau_m_ro[tid]);
}

// -------- K1: currents = einsum('btrf,f->btr') + b_in, written transposed [t][r][b] --------
__global__ void k_currents(const float* __restrict__ input,
                           const float* __restrict__ w_in,
                           const float* __restrict__ b_in) {
    int warp = blockIdx.x * (blockDim.x >> 5) + (threadIdx.x >> 5);
    int lane = threadIdx.x & 31;
    // warp -> linear (b,t,r) matching input layout
    // total warps = B*T*R = 3,276,800
    long o = (long)warp;
    const float4* in4 = reinterpret_cast<const float4*>(input + o * F_N);
    float4 v = in4[lane];
    float4 w = reinterpret_cast<const float4*>(w_in)[lane];
    float s = v.x * w.x + v.y * w.y + v.z * w.z + v.w * w.w;
    #pragma unroll
    for (int off = 16; off > 0; off >>= 1) s += __shfl_xor_sync(0xFFFFFFFFu, s, off);
    if (lane == 0) {
        int r = warp % R_N;
        int t = (warp / R_N) % T_STEPS;
        int b = warp / (R_N * T_STEPS);
        g_curT[(t * R_N + r) * B_N + b] = s + b_in[0];
    }
}

// -------- K1b: gating transpose [b][t][r] -> [t][r][b] --------
__global__ void k_gtrans(const float* __restrict__ gating) {
    int tid = blockIdx.x * blockDim.x + threadIdx.x;
    if (tid >= B_N * T_STEPS * R_N) return;
    int r = tid % R_N;
    int t = (tid / R_N) % T_STEPS;
    int b = tid / (R_N * T_STEPS);
    g_gT[(t * R_N + r) * B_N + b] = gating[tid];
}

// -------- K2: fused step kernel --------
// grid = 257 blocks x 256 threads. Blocks 0..255: recurrent step t (8 units each).
// Block 256: readout LIF for step t-1 (reads the spike buffer step t-1 wrote;
// step-t blocks write the OTHER buffer, so no race).
__global__ void k_step(int t,
                       const float* __restrict__ b_rnn,
                       const float* __restrict__ w_ro,
                       const float* __restrict__ b_ro,
                       float* __restrict__ out_outputs,   // [B][C][T]
                       float* __restrict__ out_spikes) {  // [B][R][T]
    if (blockIdx.x == 256) {
        if (t == 0) return;
        int tr = t - 1;
        const float* spk = g_spk[t & 1];   // buffer written by step t-1
        for (int tid = threadIdx.x; tid < B_N * C_N; tid += blockDim.x) {
            int b = tid / C_N, c = tid % C_N;
            float acc = 0.f;
            #pragma unroll 4
            for (int r = 0; r < R_N; r++)
                acc += spk[r * B_N + b] * w_ro[c * R_N + r];
            acc += b_ro[c];
            float ao = g_alphao[c];
            float m  = g_memo[tid];
            float so = g_spko[tid];
            m = m * ao + (1.f - ao) * acc - VTH * so;
            so = (m - VTH) > 0.f ? 1.f : 0.f;
            g_memo[tid] = m;
            g_spko[tid] = so;
            out_outputs[(b * C_N + c) * T_STEPS + tr] = m;
        }
        return;
    }
    if (t == T_STEPS) return;

    __shared__ float2 swp[8][NZ];   // (weight, idx-as-bits)
    __shared__ float  sdnew[8][B_N];

    int lane = threadIdx.x & 31;    // batch
    int u    = threadIdx.x >> 5;    // unit within block
    int j    = blockIdx.x * 8 + u;  // global unit

    // stage compacted weights for this block's 8 units
    for (int i = threadIdx.x; i < 8 * NZ; i += blockDim.x) {
        int uu = i >> 8, ii = i & (NZ - 1);
        int jj = blockIdx.x * 8 + uu;
        swp[uu][ii] = make_float2(g_wc[jj * NZ + ii], __int_as_float(g_ic[jj * NZ + ii]));
    }
    __syncthreads();

    const float* curt = g_curT + t * R_N * B_N;
    const float* spkp = g_spk[t & 1];
    float*       spkc = g_spk[(t + 1) & 1];

    int ncur = g_ncur[j];
    float acc = 0.f;
    int i = 0;
    #pragma unroll 4
    for (; i < ncur; i++) {
        float2 p = swp[u][i];
        acc += p.x * curt[__float_as_int(p.y) * B_N + lane];
    }
    #pragma unroll 4
    for (; i < NZ; i++) {
        float2 p = swp[u][i];
        acc += p.x * spkp[__float_as_int(p.y) * B_N + lane];
    }
    float proj = acc + b_rnn[j];

    int r = j >> 2;
    float beta = g_beta[j];
    float din  = g_din[j * B_N + lane];
    float dnew = beta * din + (1.f - beta) * proj;
    sdnew[u][lane] = dnew;
    float g = g_gT[(t * R_N + r) * B_N + lane];
    g_din[j * B_N + lane] = g * dnew + (1.f - g) * din;
    __syncthreads();

    if (u < 2) {
        int n = blockIdx.x * 2 + u;  // neuron
        float lin = sdnew[u * 4][lane] + sdnew[u * 4 + 1][lane]
                  + sdnew[u * 4 + 2][lane] + sdnew[u * 4 + 3][lane];
        float a   = g_alpha[n];
        float m   = g_mem[n * B_N + lane];
        float sp  = spkp[n * B_N + lane];
        float mnew = m * a + (1.f - a) * lin - VTH * sp;
        float snew = (mnew - VTH) > 0.f ? 1.f : 0.f;
        float gg = g_gT[(t * R_N + n) * B_N + lane];
        g_mem[n * B_N + lane] = gg * mnew + (1.f - gg) * m;
        float sout = gg * snew + (1.f - gg) * sp;
        spkc[n * B_N + lane] = sout;
        out_spikes[(lane * R_N + n) * T_STEPS + t] = sout;
    }
}

extern "C" void kernel_launch(void* const* d_in, const int* in_sizes, int n_in,
                              void* d_out, int out_size) {
    const float* input   = (const float*)d_in[0];   // [32,200,512,128]
    const float* gating  = (const float*)d_in[1];   // [32,200,512]
    const float* w_in    = (const float*)d_in[2];   // [128]
    const float* b_in    = (const float*)d_in[3];   // [1]
    const float* w_rnn   = (const float*)d_in[4];   // [2048,1024]
    const float* b_rnn   = (const float*)d_in[5];   // [2048]
    const float* tau_m   = (const float*)d_in[6];   // [512]
    const float* tau_n   = (const float*)d_in[7];   // [512,4]
    const float* w_ro    = (const float*)d_in[8];   // [10,512]
    const float* b_ro    = (const float*)d_in[9];   // [10]
    const float* tau_mro = (const float*)d_in[10];  // [10]
    const float* mask    = (const float*)d_in[11];  // [2048,1024]

    float* out_outputs = (float*)d_out;                       // B*C*T = 64000
    float* out_spikes  = (float*)d_out + B_N * C_N * T_STEPS; // B*R*T

    k_compact<<<U_N, 32>>>(w_rnn, mask);
    k_init<<<(U_N * B_N + 255) / 256, 256>>>(tau_m, tau_n, tau_mro);

    int warps = B_N * T_STEPS * R_N;               // 3,276,800
    k_currents<<<warps / 8, 256>>>(input, w_in, b_in);
    k_gtrans<<<(B_N * T_STEPS * R_N + 255) / 256, 256>>>(gating);

    for (int t = 0; t <= T_STEPS; t++)
        k_step<<<257, 256>>>(t, b_rnn, w_ro, b_ro, out_outputs, out_spikes);
}

// round 3
// speedup vs baseline: 3.8896x; 3.8896x over previous
#include <cuda_runtime.h>

#define T_STEPS 200
#define R_N 512
#define BR_N 4
#define B_N 32
#define F_N 128
#define C_N 10
#define U_N 2048   /* R*BR */
#define K2 1024    /* 2R   */
#define NZ 256     /* nonzeros per unit (mask guarantees) */
#define VTH 0.5f

// -------- persistent device scratch (allocation-free rule) --------
// unified activation buffer: [t][k][b] where k<512 = currents(t), k>=512 = spikes(t-1)
__device__ float  g_actT[(T_STEPS + 1) * K2 * B_N];    // 26.3 MB
__device__ float  g_gT[T_STEPS * R_N * B_N];           // gating transposed [t][r][b]
__device__ float2 g_wi[U_N * NZ];                      // (weight, byte-offset-as-float-bits)
__device__ float  g_mem[R_N * B_N];                    // soma membrane [r][b]
__device__ float  g_din[U_N * B_N];                    // dendritic state [unit][b]
__device__ float  g_memo[B_N * C_N];                   // readout membrane
__device__ float  g_spko[B_N * C_N];                   // readout spike
__device__ float  g_alpha[R_N];
__device__ float  g_beta[U_N];
__device__ float  g_alphao[C_N];

__device__ __forceinline__ float sigmoidf(float x) { return 1.f / (1.f + expf(-x)); }

// -------- K0: compact masked weights (one warp per output unit) --------
__global__ void k_compact(const float* __restrict__ w_rnn,
                          const float* __restrict__ mask) {
    int j = blockIdx.x;          // 0..2047
    int lane = threadIdx.x;      // 0..31
    int base = 0;
    for (int c = 0; c < 32; c++) {
        int k = c * 32 + lane;
        float m = mask[j * K2 + k];
        bool nz = (m != 0.f);
        unsigned bal = __ballot_sync(0xFFFFFFFFu, nz);
        int pos = base + __popc(bal & ((1u << lane) - 1u));
        if (nz) {
            // byte offset into the unified activation row block: k * B_N * 4
            g_wi[j * NZ + pos] = make_float2(w_rnn[j * K2 + k] * m,
                                             __int_as_float(k * (B_N * 4)));
        }
        base += __popc(bal);
    }
}

// -------- K0b: zero state + precompute decays --------
__global__ void k_init(const float* __restrict__ tau_m,
                       const float* __restrict__ tau_n,
                       const float* __restrict__ tau_m_ro) {
    int tid = blockIdx.x * blockDim.x + threadIdx.x;
    if (tid < U_N * B_N) g_din[tid] = 0.f;
    if (tid < R_N * B_N) {
        g_mem[tid] = 0.f;
        g_actT[R_N * B_N + tid] = 0.f;   // spikes region of t=0 slab
    }
    if (tid < B_N * C_N) { g_memo[tid] = 0.f; g_spko[tid] = 0.f; }
    if (tid < R_N)  g_alpha[tid]  = sigmoidf(tau_m[tid]);
    if (tid < U_N)  g_beta[tid]   = sigmoidf(tau_n[tid]);   // tau_n row-major [R][BR] == unit idx
    if (tid < C_N)  g_alphao[tid] = sigmoidf(tau_m_ro[tid]);
}

// -------- K1: currents = einsum('btrf,f->btr') + b_in, into g_actT[t][r][b] --------
__global__ void k_currents(const float* __restrict__ input,
                           const float* __restrict__ w_in,
                           const float* __restrict__ b_in) {
    int warp = blockIdx.x * (blockDim.x >> 5) + (threadIdx.x >> 5);
    int lane = threadIdx.x & 31;
    long o = (long)warp;   // linear (b,t,r), total = B*T*R
    const float4* in4 = reinterpret_cast<const float4*>(input + o * F_N);
    float4 v = in4[lane];
    float4 w = reinterpret_cast<const float4*>(w_in)[lane];
    float s = v.x * w.x + v.y * w.y + v.z * w.z + v.w * w.w;
    #pragma unroll
    for (int off = 16; off > 0; off >>= 1) s += __shfl_xor_sync(0xFFFFFFFFu, s, off);
    if (lane == 0) {
        int r = warp % R_N;
        int t = (warp / R_N) % T_STEPS;
        int b = warp / (R_N * T_STEPS);
        g_actT[(t * K2 + r) * B_N + b] = s + b_in[0];
    }
}

// -------- K1b: gating transpose [b][t][r] -> [t][r][b] --------
__global__ void k_gtrans(const float* __restrict__ gating) {
    int tid = blockIdx.x * blockDim.x + threadIdx.x;
    if (tid >= B_N * T_STEPS * R_N) return;
    int r = tid % R_N;
    int t = (tid / R_N) % T_STEPS;
    int b = tid / (R_N * T_STEPS);
    g_gT[(t * R_N + r) * B_N + b] = gating[tid];
}

// -------- K2: fused step kernel --------
// grid = 266 blocks x 256 threads.
// Blocks 0..255: recurrent step t (8 units each), skip at t==T.
// Blocks 256..265: readout LIF class c=blockIdx-256 for step t-1, skip at t==0.
__global__ void __launch_bounds__(256)
k_step(int t,
       const float* __restrict__ b_rnn,
       const float* __restrict__ w_ro,
       const float* __restrict__ b_ro,
       float* __restrict__ out_outputs,   // [B][C][T]
       float* __restrict__ out_spikes) {  // [B][R][T]
    if (blockIdx.x >= 256) {
        // ---- readout LIF for step t-1 ----
        if (t == 0) return;
        int c = blockIdx.x - 256;
        int tid = threadIdx.x;
        int b = tid & 31;
        int chunk = tid >> 5;                 // 0..7, 64 r each
        const float* spk = g_actT + (long)t * K2 * B_N + R_N * B_N;  // spikes(t-1)
        const float* wr = w_ro + c * R_N;
        float acc = 0.f;
        int r0 = chunk * 64;
        #pragma unroll 16
        for (int i = 0; i < 64; i++)
            acc += spk[(r0 + i) * B_N + b] * wr[r0 + i];
        __shared__ float sacc[8][B_N];
        sacc[chunk][b] = acc;
        __syncthreads();
        if (tid < B_N) {
            float s = sacc[0][tid] + sacc[1][tid] + sacc[2][tid] + sacc[3][tid]
                    + sacc[4][tid] + sacc[5][tid] + sacc[6][tid] + sacc[7][tid]
                    + b_ro[c];
            float ao = g_alphao[c];
            int oi = tid * C_N + c;
            float m  = g_memo[oi];
            float so = g_spko[oi];
            m = m * ao + (1.f - ao) * s - VTH * so;
            so = (m - VTH) > 0.f ? 1.f : 0.f;
            g_memo[oi] = m;
            g_spko[oi] = so;
            out_outputs[(tid * C_N + c) * T_STEPS + (t - 1)] = m;
        }
        return;
    }
    if (t == T_STEPS) return;

    __shared__ float2 swp[8][NZ];
    __shared__ float  sdnew[8][B_N];

    int lane = threadIdx.x & 31;    // batch
    int u    = threadIdx.x >> 5;    // unit within block
    int j    = blockIdx.x * 8 + u;  // global unit

    // stage compacted (w, byteoff) pairs for this block's 8 units
    {
        const float2* src = g_wi + (long)blockIdx.x * 8 * NZ;
        for (int i = threadIdx.x; i < 8 * NZ; i += 256)
            swp[i >> 8][i & (NZ - 1)] = src[i];
    }
    __syncthreads();

    const char*  base = (const char*)(g_actT + (long)t * K2 * B_N) + lane * 4;
    const float* spkp = g_actT + (long)t * K2 * B_N + R_N * B_N;       // spikes(t-1)
    float*       spkc = g_actT + (long)(t + 1) * K2 * B_N + R_N * B_N; // spikes(t)

    float acc = 0.f;
    #pragma unroll 32
    for (int i = 0; i < NZ; i++) {
        float2 p = swp[u][i];
        acc += p.x * *(const float*)(base + __float_as_int(p.y));
    }
    float proj = acc + b_rnn[j];

    int r = j >> 2;
    float beta = g_beta[j];
    float din  = g_din[j * B_N + lane];
    float dnew = beta * din + (1.f - beta) * proj;
    sdnew[u][lane] = dnew;
    float g = g_gT[(t * R_N + r) * B_N + lane];
    g_din[j * B_N + lane] = g * dnew + (1.f - g) * din;
    __syncthreads();

    if (u < 2) {
        int n = blockIdx.x * 2 + u;  // neuron
        float lin = sdnew[u * 4][lane] + sdnew[u * 4 + 1][lane]
                  + sdnew[u * 4 + 2][lane] + sdnew[u * 4 + 3][lane];
        float a   = g_alpha[n];
        float m   = g_mem[n * B_N + lane];
        float sp  = spkp[n * B_N + lane];
        float mnew = m * a + (1.f - a) * lin - VTH * sp;
        float snew = (mnew - VTH) > 0.f ? 1.f : 0.f;
        float gg = g_gT[(t * R_N + n) * B_N + lane];
        g_mem[n * B_N + lane] = gg * mnew + (1.f - gg) * m;
        float sout = gg * snew + (1.f - gg) * sp;
        spkc[n * B_N + lane] = sout;
        out_spikes[(lane * R_N + n) * T_STEPS + t] = sout;
    }
}

extern "C" void kernel_launch(void* const* d_in, const int* in_sizes, int n_in,
                              void* d_out, int out_size) {
    const float* input   = (const float*)d_in[0];   // [32,200,512,128]
    const float* gating  = (const float*)d_in[1];   // [32,200,512]
    const float* w_in    = (const float*)d_in[2];   // [128]
    const float* b_in    = (const float*)d_in[3];   // [1]
    const float* w_rnn   = (const float*)d_in[4];   // [2048,1024]
    const float* b_rnn   = (const float*)d_in[5];   // [2048]
    const float* tau_m   = (const float*)d_in[6];   // [512]
    const float* tau_n   = (const float*)d_in[7];   // [512,4]
    const float* w_ro    = (const float*)d_in[8];   // [10,512]
    const float* b_ro    = (const float*)d_in[9];   // [10]
    const float* tau_mro = (const float*)d_in[10];  // [10]
    const float* mask    = (const float*)d_in[11];  // [2048,1024]

    float* out_outputs = (float*)d_out;                       // B*C*T = 64000
    float* out_spikes  = (float*)d_out + B_N * C_N * T_STEPS; // B*R*T

    k_compact<<<U_N, 32>>>(w_rnn, mask);
    k_init<<<(U_N * B_N + 255) / 256, 256>>>(tau_m, tau_n, tau_mro);

    int warps = B_N * T_STEPS * R_N;               // 3,276,800
    k_currents<<<warps / 8, 256>>>(input, w_in, b_in);
    k_gtrans<<<(B_N * T_STEPS * R_N + 255) / 256, 256>>>(gating);

    for (int t = 0; t <= T_STEPS; t++)
        k_step<<<266, 256>>>(t, b_rnn, w_ro, b_ro, out_outputs, out_spikes);
}